// round 5
// baseline (speedup 1.0000x reference)
#include <cuda_runtime.h>
#include <cuda_bf16.h>
#include <cstdint>

// GraphConv: out = segment_sum(x[src])@Wn^T + b_n + x@Wr^T + b_r
// Linearity rewrite: y = x@Wn^T ; out = x@Wr^T + (b_n+b_r) ; out[dst] += y[src]
//
// Inputs (metadata order):
//  0: x          float32 [100000,128]
//  1: edge_index int32 OR int64 [2,625000]  (JAX default config downcasts
//     jnp.int64 -> int32; we detect the element width on-device)
//  2: W_neigh    float32 [128,128]   (stored [out,in])
//  3: b_neigh    float32 [128]
//  4: W_root     float32 [128,128]
//  5: b_root     float32 [128]
// out: float32 [100000,128]

#define N_FEAT 128
#define BM 64          // node rows per block
#define BN 256         // both weight matrices side by side
#define BS_STRIDE 260  // padded, multiple of 4 (16B alignment for LDS.128)
#define AS_STRIDE 68   // padded, multiple of 4

__device__ float g_y[100000 * N_FEAT];  // scratch: x @ Wn^T

// ---------------------------------------------------------------------------
// Fused dual-GEMM: C[M, 0:128]   = x@Wr^T + (b_n+b_r) -> d_out
//                  C[M, 128:256] = x@Wn^T             -> g_y
// ---------------------------------------------------------------------------
__global__ void __launch_bounds__(256, 1)
gemm_dual_kernel(const float* __restrict__ x,
                 const float* __restrict__ Wn,
                 const float* __restrict__ bn,
                 const float* __restrict__ Wr,
                 const float* __restrict__ br,
                 float* __restrict__ out,
                 int N)
{
    extern __shared__ float smem[];
    float* Bs = smem;                       // [128][BS_STRIDE]  Bs[k][j] = W[j][k]
    float* As = Bs + N_FEAT * BS_STRIDE;    // [128][AS_STRIDE]  As[k][m]
    __shared__ float bias_s[N_FEAT];

    const int tid = threadIdx.x;
    const int tn  = tid & 31;   // column group: cols 8*tn .. 8*tn+7
    const int tm  = tid >> 5;   // row group:    rows 8*tm .. 8*tm+7
    const int mBase = blockIdx.x * BM;

    // ---- combined weights into shared: cols 0..127 = Wr^T, 128..255 = Wn^T ----
    #pragma unroll 4
    for (int idx = tid; idx < N_FEAT * BN; idx += 256) {
        int j = idx >> 7;       // 0..255
        int k = idx & 127;
        float w = (j < 128) ? __ldg(&Wr[j * 128 + k]) : __ldg(&Wn[(j - 128) * 128 + k]);
        Bs[k * BS_STRIDE + j] = w;
    }
    if (tid < N_FEAT) bias_s[tid] = __ldg(&bn[tid]) + __ldg(&br[tid]);

    // ---- A tile transposed: As[k][m] = x[mBase+m][k] ----
    #pragma unroll
    for (int it = 0; it < 8; it++) {
        int idx = tid + it * 256;       // 0..2047
        int r   = idx >> 5;             // row 0..63
        int c4  = idx & 31;             // float4 col 0..31
        int node = mBase + r;
        float4 v = make_float4(0.f, 0.f, 0.f, 0.f);
        if (node < N)
            v = reinterpret_cast<const float4*>(x + (size_t)node * N_FEAT)[c4];
        int k0 = c4 * 4;
        As[(k0 + 0) * AS_STRIDE + r] = v.x;
        As[(k0 + 1) * AS_STRIDE + r] = v.y;
        As[(k0 + 2) * AS_STRIDE + r] = v.z;
        As[(k0 + 3) * AS_STRIDE + r] = v.w;
    }
    __syncthreads();

    // ---- main loop: 8x8 micro-tile per thread ----
    float acc[8][8];
    #pragma unroll
    for (int i = 0; i < 8; i++)
        #pragma unroll
        for (int j = 0; j < 8; j++) acc[i][j] = 0.f;

    #pragma unroll
    for (int k = 0; k < N_FEAT; k++) {
        const float4 a0 = *reinterpret_cast<const float4*>(&As[k * AS_STRIDE + tm * 8]);
        const float4 a1 = *reinterpret_cast<const float4*>(&As[k * AS_STRIDE + tm * 8 + 4]);
        const float4 b0 = *reinterpret_cast<const float4*>(&Bs[k * BS_STRIDE + tn * 8]);
        const float4 b1 = *reinterpret_cast<const float4*>(&Bs[k * BS_STRIDE + tn * 8 + 4]);
        float a[8] = {a0.x, a0.y, a0.z, a0.w, a1.x, a1.y, a1.z, a1.w};
        float b[8] = {b0.x, b0.y, b0.z, b0.w, b1.x, b1.y, b1.z, b1.w};
        #pragma unroll
        for (int i = 0; i < 8; i++)
            #pragma unroll
            for (int j = 0; j < 8; j++)
                acc[i][j] += a[i] * b[j];
    }

    // ---- store ----
    const int colBase = tn * 8;             // 0..248
    const bool toOut = (colBase < 128);
    #pragma unroll
    for (int i = 0; i < 8; i++) {
        int node = mBase + tm * 8 + i;
        if (node >= N) break;
        if (toOut) {
            float4 v0 = make_float4(acc[i][0] + bias_s[colBase + 0],
                                    acc[i][1] + bias_s[colBase + 1],
                                    acc[i][2] + bias_s[colBase + 2],
                                    acc[i][3] + bias_s[colBase + 3]);
            float4 v1 = make_float4(acc[i][4] + bias_s[colBase + 4],
                                    acc[i][5] + bias_s[colBase + 5],
                                    acc[i][6] + bias_s[colBase + 6],
                                    acc[i][7] + bias_s[colBase + 7]);
            float* p = out + (size_t)node * N_FEAT + colBase;
            reinterpret_cast<float4*>(p)[0] = v0;
            reinterpret_cast<float4*>(p)[1] = v1;
        } else {
            float4 v0 = make_float4(acc[i][0], acc[i][1], acc[i][2], acc[i][3]);
            float4 v1 = make_float4(acc[i][4], acc[i][5], acc[i][6], acc[i][7]);
            float* p = g_y + (size_t)node * N_FEAT + (colBase - 128);
            reinterpret_cast<float4*>(p)[0] = v0;
            reinterpret_cast<float4*>(p)[1] = v1;
        }
    }
}

// ---------------------------------------------------------------------------
// Scatter: out[dst] += y[src].  One edge per warp (e warp-uniform -> whole-warp
// exit, shfl always fully active).  Edge-index element width detected on
// device: reads bytes 0..63 of ei as int64; with int32 data each word packs
// two random indices so its int64 value >= 2^32 w.p. ~1-1e-5 per word.
// ---------------------------------------------------------------------------
__global__ void __launch_bounds__(256)
scatter_kernel(const void* __restrict__ ei_raw,
               float* __restrict__ out,
               int E, int N)
{
    const int e = blockIdx.x * 8 + (threadIdx.x >> 5);   // warp-uniform
    if (e >= E) return;                                   // whole-warp exit
    const int lane = threadIdx.x & 31;

    // ---- dtype probe (bytes 0..63: inside both 8E-byte and 16E-byte buffers)
    const long long* ei64 = (const long long*)ei_raw;
    const int*       ei32 = (const int*)ei_raw;
    long long probe = (lane < 8) ? __ldg(&ei64[lane]) : 0;
    bool ok = (lane < 8) ? (probe >= 0 && probe < (long long)N) : true;
    const bool is64 = ((__ballot_sync(0xFFFFFFFFu, ok) & 0xFFu) == 0xFFu);

    long long src = 0, dst = 0;
    if (lane == 0) {
        if (is64) { src = __ldg(&ei64[e]); dst = __ldg(&ei64[E + e]); }
        else      { src = __ldg(&ei32[e]); dst = __ldg(&ei32[E + e]); }
    }
    src = __shfl_sync(0xFFFFFFFFu, src, 0);
    dst = __shfl_sync(0xFFFFFFFFu, dst, 0);

    // branchless clamp: second-line defense
    long long nmax = (long long)N - 1;
    src = src < 0 ? 0 : (src > nmax ? nmax : src);
    dst = dst < 0 ? 0 : (dst > nmax ? nmax : dst);

    float4 v = reinterpret_cast<const float4*>(g_y + (size_t)src * N_FEAT)[lane];
    float* p = out + (size_t)dst * N_FEAT + lane * 4;
    asm volatile("red.global.add.v4.f32 [%0], {%1, %2, %3, %4};"
                 :: "l"(p), "f"(v.x), "f"(v.y), "f"(v.z), "f"(v.w)
                 : "memory");
}

// ---------------------------------------------------------------------------
extern "C" void kernel_launch(void* const* d_in, const int* in_sizes, int n_in,
                              void* d_out, int out_size)
{
    const float* x  = (const float*)d_in[0];
    const void*  ei = d_in[1];
    const float* Wn = (const float*)d_in[2];
    const float* bn = (const float*)d_in[3];
    const float* Wr = (const float*)d_in[4];
    const float* br = (const float*)d_in[5];
    float* out = (float*)d_out;

    const int N = in_sizes[0] / N_FEAT;
    const int E = in_sizes[1] / 2;      // element count / 2 regardless of width

    const size_t smem_bytes =
        (size_t)(N_FEAT * BS_STRIDE + N_FEAT * AS_STRIDE) * sizeof(float);
    cudaFuncSetAttribute(gemm_dual_kernel,
                         cudaFuncAttributeMaxDynamicSharedMemorySize,
                         (int)smem_bytes);

    int gemm_blocks = (N + BM - 1) / BM;
    gemm_dual_kernel<<<gemm_blocks, 256, smem_bytes>>>(x, Wn, bn, Wr, br, out, N);

    int scat_blocks = (E + 7) / 8;   // 8 warps (= 8 edges) per block
    scatter_kernel<<<scat_blocks, 256>>>(ei, out, E, N);
}

// round 7
// speedup vs baseline: 2.7510x; 2.7510x over previous
#include <cuda_runtime.h>
#include <cuda_bf16.h>
#include <cstdint>

// GraphConv: out = segment_sum(x[src])@Wn^T + b_n + x@Wr^T + b_r
// y = x@Wn^T ; out = x@Wr^T + (b_n+b_r) ; out[dst] += y[src]
// GEMM via mma.sync m16n8k16 bf16 (sm_80+ PTX, works on bare sm_100 target)
// with hi/lo split: D = Ah*Bh + Ah*Bl + Al*Bh  (error ~2^-16)
//
// Inputs: 0:x f32[100000,128] 1:edge_index int32/int64[2,625000]
//         2:W_neigh f32[128,128] 3:b_neigh[128] 4:W_root f32[128,128] 5:b_root[128]

#define N_FEAT 128
#define BM 128
#define KDIM 128
#define SSTRIDE 136   // bf16 elements per row (128 + 8 pad) -> 272B, conflict-free ldmatrix

__device__ float g_y[100000 * N_FEAT];  // x @ Wn^T

__device__ __forceinline__ uint32_t smem_u32(const void* p) {
    uint32_t a;
    asm("{ .reg .u64 t; cvta.to.shared.u64 t, %1; cvt.u32.u64 %0, t; }" : "=r"(a) : "l"(p));
    return a;
}

#define LDMATRIX_X4(r0, r1, r2, r3, addr) \
    asm volatile("ldmatrix.sync.aligned.m8n8.x4.shared.b16 {%0,%1,%2,%3}, [%4];" \
                 : "=r"(r0), "=r"(r1), "=r"(r2), "=r"(r3) : "r"(addr))

#define MMA_BF16(c0, c1, c2, c3, a0, a1, a2, a3, b0, b1) \
    asm volatile("mma.sync.aligned.m16n8k16.row.col.f32.bf16.bf16.f32 " \
                 "{%0,%1,%2,%3}, {%4,%5,%6,%7}, {%8,%9}, {%0,%1,%2,%3};" \
                 : "+f"(c0), "+f"(c1), "+f"(c2), "+f"(c3) \
                 : "r"(a0), "r"(a1), "r"(a2), "r"(a3), "r"(b0), "r"(b1))

// ---------------------------------------------------------------------------
// GEMM: C = x @ W^T (+ bias).  blockIdx.y: 0 -> Wr -> out (+bn+br), 1 -> Wn -> g_y
// CTA: 128 rows x 128 cols, K=128.  8 warps (2 x 4), warp tile 64 x 32.
// ---------------------------------------------------------------------------
__global__ void __launch_bounds__(256, 1)
gemm_mma_kernel(const float* __restrict__ x,
                const float* __restrict__ Wn,
                const float* __restrict__ bn,
                const float* __restrict__ Wr,
                const float* __restrict__ br,
                float* __restrict__ out,
                int N)
{
    extern __shared__ __nv_bfloat16 smem[];
    __nv_bfloat16* Ah = smem;                    // [128][SSTRIDE]
    __nv_bfloat16* Al = Ah + BM * SSTRIDE;
    __nv_bfloat16* Bh = Al + BM * SSTRIDE;       // [128 n][SSTRIDE k]
    __nv_bfloat16* Bl = Bh + N_FEAT * SSTRIDE;
    __shared__ float bias_s[N_FEAT];

    const int tid = threadIdx.x;
    const int wid = tid >> 5, lane = tid & 31;
    const int wm = wid >> 2;        // 0..1  -> rows wm*64..+63
    const int wn = wid & 3;         // 0..3  -> cols wn*32..+31
    const int mBase = blockIdx.x * BM;
    const bool isRoot = (blockIdx.y == 0);
    const float* W = isRoot ? Wr : Wn;

    if (tid < N_FEAT) bias_s[tid] = isRoot ? (__ldg(&bn[tid]) + __ldg(&br[tid])) : 0.f;

    // ---- fill A (x tile) and B (W) hi/lo, padded row-major ----
    #pragma unroll
    for (int it = 0; it < 16; it++) {
        int idx = tid + it * 256;          // 0..4095
        int r  = idx >> 5;                 // row 0..127
        int c4 = idx & 31;                 // float4 col
        int k0 = c4 * 4;

        // A: x[mBase+r][k0..k0+3]
        float4 va = make_float4(0.f, 0.f, 0.f, 0.f);
        if (mBase + r < N)
            va = reinterpret_cast<const float4*>(x + (size_t)(mBase + r) * N_FEAT)[c4];
        // B: W[r][k0..k0+3]
        float4 vb = reinterpret_cast<const float4*>(W + (size_t)r * N_FEAT)[c4];

        __nv_bfloat162 ah, al, bh, bl;
        #pragma unroll
        for (int h = 0; h < 2; h++) {
            float a0 = h ? va.z : va.x, a1 = h ? va.w : va.y;
            float b0 = h ? vb.z : vb.x, b1 = h ? vb.w : vb.y;
            ah.x = __float2bfloat16(a0); ah.y = __float2bfloat16(a1);
            al.x = __float2bfloat16(a0 - __bfloat162float(ah.x));
            al.y = __float2bfloat16(a1 - __bfloat162float(ah.y));
            bh.x = __float2bfloat16(b0); bh.y = __float2bfloat16(b1);
            bl.x = __float2bfloat16(b0 - __bfloat162float(bh.x));
            bl.y = __float2bfloat16(b1 - __bfloat162float(bh.y));
            int o = r * SSTRIDE + k0 + h * 2;
            *reinterpret_cast<__nv_bfloat162*>(Ah + o) = ah;
            *reinterpret_cast<__nv_bfloat162*>(Al + o) = al;
            *reinterpret_cast<__nv_bfloat162*>(Bh + o) = bh;
            *reinterpret_cast<__nv_bfloat162*>(Bl + o) = bl;
        }
    }
    __syncthreads();

    // ---- accumulators: 4 m-tiles x 4 n-tiles x 4 regs ----
    float acc[4][4][4];
    #pragma unroll
    for (int i = 0; i < 4; i++)
        #pragma unroll
        for (int j = 0; j < 4; j++)
            #pragma unroll
            for (int q = 0; q < 4; q++) acc[i][j][q] = 0.f;

    // ldmatrix lane addressing (constant across k-steps except k offset):
    // A (m16k16 tile): row = m0 + (lane&7) + ((lane>>3)&1)*8 ; k += (lane>>4)*8
    const int aRow = (lane & 7) + ((lane >> 3) & 1) * 8;
    const int aK   = (lane >> 4) * 8;
    // B from [n][k]: n = n0 + (lane&7) + (lane>>4)*8 ; k += ((lane>>3)&1)*8
    const int bRow = (lane & 7) + (lane >> 4) * 8;
    const int bK   = ((lane >> 3) & 1) * 8;

    const uint32_t sAh = smem_u32(Ah), sAl = smem_u32(Al);
    const uint32_t sBh = smem_u32(Bh), sBl = smem_u32(Bl);

    #pragma unroll
    for (int pass = 0; pass < 3; pass++) {
        const uint32_t aBase = (pass == 2) ? sAl : sAh;
        const uint32_t bBase = (pass == 1) ? sBl : sBh;

        #pragma unroll
        for (int ks = 0; ks < KDIM / 16; ks++) {
            const int k = ks * 16;
            uint32_t a[4][4];
            #pragma unroll
            for (int i = 0; i < 4; i++) {
                int row = wm * 64 + i * 16 + aRow;
                uint32_t addr = aBase + (uint32_t)(row * SSTRIDE + k + aK) * 2;
                LDMATRIX_X4(a[i][0], a[i][1], a[i][2], a[i][3], addr);
            }
            uint32_t b[2][4];   // b[j2]: regs 0,1 -> n-tile 2*j2 ; regs 2,3 -> 2*j2+1
            #pragma unroll
            for (int j2 = 0; j2 < 2; j2++) {
                int n = wn * 32 + j2 * 16 + bRow;
                uint32_t addr = bBase + (uint32_t)(n * SSTRIDE + k + bK) * 2;
                LDMATRIX_X4(b[j2][0], b[j2][1], b[j2][2], b[j2][3], addr);
            }
            #pragma unroll
            for (int i = 0; i < 4; i++)
                #pragma unroll
                for (int j = 0; j < 4; j++) {
                    uint32_t b0 = b[j >> 1][(j & 1) * 2 + 0];
                    uint32_t b1 = b[j >> 1][(j & 1) * 2 + 1];
                    MMA_BF16(acc[i][j][0], acc[i][j][1], acc[i][j][2], acc[i][j][3],
                             a[i][0], a[i][1], a[i][2], a[i][3], b0, b1);
                }
        }
    }

    // ---- epilogue: D lane layout: d0,d1 -> (row g, col 2t,2t+1); d2,d3 -> row g+8 ----
    const int g = lane >> 2, t = lane & 3;
    float* dstBase = isRoot ? out : g_y;
    #pragma unroll
    for (int i = 0; i < 4; i++) {
        int r0 = mBase + wm * 64 + i * 16 + g;
        #pragma unroll
        for (int j = 0; j < 4; j++) {
            int c = wn * 32 + j * 8 + 2 * t;
            float b0 = bias_s[c], b1 = bias_s[c + 1];
            if (r0 < N) {
                float2 v = make_float2(acc[i][j][0] + b0, acc[i][j][1] + b1);
                *reinterpret_cast<float2*>(dstBase + (size_t)r0 * N_FEAT + c) = v;
            }
            if (r0 + 8 < N) {
                float2 v = make_float2(acc[i][j][2] + b0, acc[i][j][3] + b1);
                *reinterpret_cast<float2*>(dstBase + (size_t)(r0 + 8) * N_FEAT + c) = v;
            }
        }
    }
}

// ---------------------------------------------------------------------------
// Scatter: out[dst] += y[src]. One edge per warp; dtype probe (int32 vs int64).
// ---------------------------------------------------------------------------
__global__ void __launch_bounds__(256)
scatter_kernel(const void* __restrict__ ei_raw,
               float* __restrict__ out,
               int E, int N)
{
    const int e = blockIdx.x * 8 + (threadIdx.x >> 5);
    if (e >= E) return;                       // whole-warp exit
    const int lane = threadIdx.x & 31;

    const long long* ei64 = (const long long*)ei_raw;
    const int*       ei32 = (const int*)ei_raw;
    long long probe = (lane < 8) ? __ldg(&ei64[lane]) : 0;
    bool ok = (lane < 8) ? (probe >= 0 && probe < (long long)N) : true;
    const bool is64 = ((__ballot_sync(0xFFFFFFFFu, ok) & 0xFFu) == 0xFFu);

    long long src = 0, dst = 0;
    if (lane == 0) {
        if (is64) { src = __ldg(&ei64[e]); dst = __ldg(&ei64[E + e]); }
        else      { src = __ldg(&ei32[e]); dst = __ldg(&ei32[E + e]); }
    }
    src = __shfl_sync(0xFFFFFFFFu, src, 0);
    dst = __shfl_sync(0xFFFFFFFFu, dst, 0);

    long long nmax = (long long)N - 1;
    src = src < 0 ? 0 : (src > nmax ? nmax : src);
    dst = dst < 0 ? 0 : (dst > nmax ? nmax : dst);

    float4 v = reinterpret_cast<const float4*>(g_y + (size_t)src * N_FEAT)[lane];
    float* p = out + (size_t)dst * N_FEAT + lane * 4;
    asm volatile("red.global.add.v4.f32 [%0], {%1, %2, %3, %4};"
                 :: "l"(p), "f"(v.x), "f"(v.y), "f"(v.z), "f"(v.w)
                 : "memory");
}

// ---------------------------------------------------------------------------
extern "C" void kernel_launch(void* const* d_in, const int* in_sizes, int n_in,
                              void* d_out, int out_size)
{
    const float* x  = (const float*)d_in[0];
    const void*  ei = d_in[1];
    const float* Wn = (const float*)d_in[2];
    const float* bn = (const float*)d_in[3];
    const float* Wr = (const float*)d_in[4];
    const float* br = (const float*)d_in[5];
    float* out = (float*)d_out;

    const int N = in_sizes[0] / N_FEAT;
    const int E = in_sizes[1] / 2;

    const size_t smem_bytes = (size_t)4 * BM * SSTRIDE * sizeof(__nv_bfloat16); // 139264
    cudaFuncSetAttribute(gemm_mma_kernel,
                         cudaFuncAttributeMaxDynamicSharedMemorySize,
                         (int)smem_bytes);

    dim3 grid((N + BM - 1) / BM, 2);
    gemm_mma_kernel<<<grid, 256, smem_bytes>>>(x, Wn, bn, Wr, br, out, N);

    int scat_blocks = (E + 7) / 8;
    scatter_kernel<<<scat_blocks, 256>>>(ei, out, E, N);
}